// round 3
// baseline (speedup 1.0000x reference)
#include <cuda_runtime.h>
#include <math_constants.h>

// Problem constants
#define BB   4
#define NN   4096
#define CIN  64
#define COUT 128
#define KP   15
#define KNNK 16
#define KDIM (KP * CIN)   // 960

// ---------------- device scratch (no cudaMalloc allowed) ----------------
__device__ float4 g_coordsT[BB * NN];                 // (x,y,z,|c|^2) point-major
__device__ float  g_featT[BB * NN * CIN];             // features point-major
__device__ int    g_nbr[BB * NN * KNNK];              // knn indices
__device__ float  g_agg[(size_t)BB * NN * KDIM];      // aggregated features (63 MB)

// f32x2 packed-fma helpers
__device__ __forceinline__ unsigned long long pack2(float x) {
    unsigned long long r;
    asm("mov.b64 %0, {%1, %1};" : "=l"(r) : "f"(x));
    return r;
}
__device__ __forceinline__ void fma2(unsigned long long& d, unsigned long long a, unsigned long long b) {
    asm("fma.rn.f32x2 %0, %1, %2, %0;" : "+l"(d) : "l"(a), "l"(b));
}

// ---------------- stage 0a: coords (B,3,N) -> float4 AoS (+|c|^2) ----------------
__global__ void prep_coords_kernel(const float* __restrict__ coords) {
    int i = blockIdx.x * blockDim.x + threadIdx.x;   // 0..16383
    int b = i >> 12;
    int n = i & (NN - 1);
    const float* cb = coords + (size_t)b * 3 * NN;
    float x = cb[n], y = cb[NN + n], z = cb[2 * NN + n];
    g_coordsT[i] = make_float4(x, y, z, x * x + y * y + z * z);
}

// ---------------- stage 0b: features (B,C,N) -> (B,N,C) tiled transpose ----------------
__global__ void prep_feat_kernel(const float* __restrict__ feats) {
    __shared__ float tile[32][33];
    int b  = blockIdx.z;
    int n0 = blockIdx.x * 32;
    int c0 = blockIdx.y * 32;
    int tx = threadIdx.x;
    int ty = threadIdx.y;
    const float* fb = feats + (size_t)b * CIN * NN;
    #pragma unroll
    for (int r = 0; r < 32; r += 8)
        tile[ty + r][tx] = fb[(size_t)(c0 + ty + r) * NN + n0 + tx];
    __syncthreads();
    float* ob = g_featT + (size_t)b * NN * CIN;
    #pragma unroll
    for (int r = 0; r < 32; r += 8)
        ob[(size_t)(n0 + ty + r) * CIN + c0 + tx] = tile[tx][ty + r];
}

// ---------------- stage 1: KNN, 8 threads/query with shared pruning threshold ----------------
// 256 threads = 32 queries x 8 slices. Slice-thread scans 512 candidates in the
// shifted metric d' = |c|^2 - 2 q.c (ordering == true d2), keeping a register
// top-16. Every 32 candidates the 8 lanes of a query share
// tau = min(worst) — a safe upper bound on the query's true 16th-NN distance —
// so nearly all candidates are rejected on the cheap path.
__global__ __launch_bounds__(256) void knn_kernel() {
    __shared__ float md[32][112];
    __shared__ int   mi[32][112];

    int tid = threadIdx.x;
    int qi  = tid >> 3;
    int si  = tid & 7;                  // == laneid & 7
    int q   = blockIdx.x * 32 + qi;
    int b   = q >> 12;
    int n   = q & (NN - 1);

    const float4* base = g_coordsT + (b << 12);
    float4 qc = __ldg(&base[n]);
    float qx2 = -2.0f * qc.x, qy2 = -2.0f * qc.y, qz2 = -2.0f * qc.z;

    float bd[KNNK];
    int   bi[KNNK];
    #pragma unroll
    for (int t = 0; t < KNNK; t++) { bd[t] = CUDART_INF_F; bi[t] = -1; }
    float worst = CUDART_INF_F;
    int   ws = 0;
    float thr = CUDART_INF_F;           // min(worst, tau)

    #pragma unroll 4
    for (int jj = 0; jj < 512; jj++) {
        if ((jj & 31) == 0) {
            // tau = min over the 8 slice lanes of this query's lane-worsts
            float w = worst;
            w = fminf(w, __shfl_xor_sync(0xffffffffu, w, 1));
            w = fminf(w, __shfl_xor_sync(0xffffffffu, w, 2));
            w = fminf(w, __shfl_xor_sync(0xffffffffu, w, 4));
            thr = fminf(w, worst);
        }
        int j = (jj << 3) | si;
        float4 c = __ldg(&base[j]);
        float d = fmaf(c.x, qx2, fmaf(c.y, qy2, fmaf(c.z, qz2, c.w)));
        if (d < thr && j != n) {
            #pragma unroll
            for (int t = 0; t < KNNK; t++)
                if (t == ws) { bd[t] = d; bi[t] = j; }
            worst = bd[0]; ws = 0;
            #pragma unroll
            for (int t = 1; t < KNNK; t++)
                if (bd[t] > worst) { worst = bd[t]; ws = t; }
            thr = fminf(thr, worst);
        }
    }

    if (si > 0) {
        #pragma unroll
        for (int t = 0; t < KNNK; t++) {
            md[qi][(si - 1) * 16 + t] = bd[t];
            mi[qi][(si - 1) * 16 + t] = bi[t];
        }
    }
    __syncthreads();

    if (si == 0) {
        for (int e = 0; e < 112; e++) {
            float d = md[qi][e];
            if (d < worst) {
                int j = mi[qi][e];
                #pragma unroll
                for (int t = 0; t < KNNK; t++)
                    if (t == ws) { bd[t] = d; bi[t] = j; }
                worst = bd[0]; ws = 0;
                #pragma unroll
                for (int t = 1; t < KNNK; t++)
                    if (bd[t] > worst) { worst = bd[t]; ws = t; }
            }
        }
        int* op = g_nbr + (size_t)q * KNNK;
        #pragma unroll
        for (int t = 0; t < KNNK; t++) op[t] = bi[t];
    }
}

// ---------------- stage 2: influence + aggregation (unchanged, ~MUFU floor) ----------------
__global__ void agg_kernel(const float* __restrict__ kpts) {
    __shared__ int   nbr[KNNK];
    __shared__ float diffs[KNNK][3];
    __shared__ float kps[KP * 3];
    __shared__ float infl[KNNK][KP];

    int m   = blockIdx.x;
    int b   = m >> 12;
    int tid = threadIdx.x;

    if (tid < KP * 3) kps[tid] = kpts[tid];
    if (tid < KNNK)   nbr[tid] = g_nbr[(size_t)m * KNNK + tid];
    __syncthreads();
    if (tid < KNNK) {
        float4 qv = g_coordsT[m];
        float4 c  = g_coordsT[(b << 12) + nbr[tid]];
        diffs[tid][0] = c.x - qv.x;
        diffs[tid][1] = c.y - qv.y;
        diffs[tid][2] = c.z - qv.z;
    }
    __syncthreads();
    for (int t = tid; t < KNNK * KP; t += 64) {
        int kk = t / KP, p = t % KP;
        float dx = diffs[kk][0] - kps[p * 3 + 0];
        float dy = diffs[kk][1] - kps[p * 3 + 1];
        float dz = diffs[kk][2] - kps[p * 3 + 2];
        float sq = dx * dx + dy * dy + dz * dz;
        infl[kk][p] = expf(-sq * 100.0f);   // 1/SIGMA^2
    }
    __syncthreads();

    float a[KP];
    #pragma unroll
    for (int p = 0; p < KP; p++) a[p] = 0.0f;

    for (int kk = 0; kk < KNNK; kk++) {
        float f = g_featT[((size_t)(b << 12) + nbr[kk]) * CIN + tid];
        #pragma unroll
        for (int p = 0; p < KP; p++)
            a[p] += infl[kk][p] * f;
    }
    float* outp = g_agg + (size_t)m * KDIM;
    #pragma unroll
    for (int p = 0; p < KP; p++)
        outp[p * CIN + tid] = a[p];
}

// ---------------- stage 3: SGEMM via fma.rn.f32x2, 64x128 tile ----------------
// out(16384x128) = Agg(16384x960) @ W(960x128). Grid 256, 256 threads,
// 2 blocks/SM (4 warps/SMSP), 4x8 microtile, M-paired accumulators,
// double-buffered smem with register prefetch.
__global__ __launch_bounds__(256) void gemm_kernel(const float* __restrict__ W,
                                                   const float* __restrict__ bias,
                                                   float* __restrict__ out) {
    __shared__ float As[2][16][64];    // As[buf][k][m]
    __shared__ float Bs[2][16][128];   // Bs[buf][k][n]

    int m0  = blockIdx.x * 64;
    int tid = threadIdx.x;
    int tx  = tid & 15;                // n group (8 cols)
    int ty  = tid >> 4;                // m group (4 rows)

    unsigned long long acc[2][8];      // [m-pair][n]
    #pragma unroll
    for (int i = 0; i < 2; i++)
        #pragma unroll
        for (int j = 0; j < 8; j++) acc[i][j] = 0ULL;

    const float* Ab = g_agg + (size_t)m0 * KDIM;
    int arow  = tid >> 2;              // 0..63
    int acol4 = (tid & 3) * 4;         // 0,4,8,12

    float4 a_r, b_r[2];

    // prologue: k-tile 0
    a_r = *(const float4*)(Ab + (size_t)arow * KDIM + acol4);
    {
        int l0 = tid, l1 = tid + 256;
        b_r[0] = *(const float4*)(W + (size_t)(l0 >> 5) * COUT + (l0 & 31) * 4);
        b_r[1] = *(const float4*)(W + (size_t)(l1 >> 5) * COUT + (l1 & 31) * 4);
    }
    {
        As[0][acol4 + 0][arow] = a_r.x; As[0][acol4 + 1][arow] = a_r.y;
        As[0][acol4 + 2][arow] = a_r.z; As[0][acol4 + 3][arow] = a_r.w;
        int l0 = tid, l1 = tid + 256;
        *(float4*)&Bs[0][l0 >> 5][(l0 & 31) * 4] = b_r[0];
        *(float4*)&Bs[0][l1 >> 5][(l1 & 31) * 4] = b_r[1];
    }
    __syncthreads();

    int buf = 0;
    const int NIT = KDIM / 16;   // 60
    for (int it = 0; it < NIT; it++) {
        if (it < NIT - 1) {
            int k0 = (it + 1) * 16;
            a_r = *(const float4*)(Ab + (size_t)arow * KDIM + k0 + acol4);
            int l0 = tid, l1 = tid + 256;
            b_r[0] = *(const float4*)(W + (size_t)(k0 + (l0 >> 5)) * COUT + (l0 & 31) * 4);
            b_r[1] = *(const float4*)(W + (size_t)(k0 + (l1 >> 5)) * COUT + (l1 & 31) * 4);
        }

        #pragma unroll
        for (int k = 0; k < 16; k++) {
            ulonglong2 A0 = *(const ulonglong2*)&As[buf][k][ty * 4];
            unsigned long long ap0 = A0.x, ap1 = A0.y;
            float4 b0 = *(const float4*)&Bs[buf][k][tx * 8];
            float4 b1 = *(const float4*)&Bs[buf][k][tx * 8 + 4];
            unsigned long long bp[8];
            bp[0] = pack2(b0.x); bp[1] = pack2(b0.y); bp[2] = pack2(b0.z); bp[3] = pack2(b0.w);
            bp[4] = pack2(b1.x); bp[5] = pack2(b1.y); bp[6] = pack2(b1.z); bp[7] = pack2(b1.w);
            #pragma unroll
            for (int j = 0; j < 8; j++) {
                fma2(acc[0][j], ap0, bp[j]);
                fma2(acc[1][j], ap1, bp[j]);
            }
        }

        if (it < NIT - 1) {
            buf ^= 1;
            As[buf][acol4 + 0][arow] = a_r.x; As[buf][acol4 + 1][arow] = a_r.y;
            As[buf][acol4 + 2][arow] = a_r.z; As[buf][acol4 + 3][arow] = a_r.w;
            int l0 = tid, l1 = tid + 256;
            *(float4*)&Bs[buf][l0 >> 5][(l0 & 31) * 4] = b_r[0];
            *(float4*)&Bs[buf][l1 >> 5][(l1 & 31) * 4] = b_r[1];
            __syncthreads();
        }
    }

    // epilogue: out is (B, C_out, N); m maps to n (point index)
    int b     = m0 >> 12;
    int nbase = (m0 & (NN - 1)) + ty * 4;
    #pragma unroll
    for (int j = 0; j < 8; j++) {
        int o = tx * 8 + j;
        float bv = __ldg(&bias[o]);
        float* op = out + ((size_t)b * COUT + o) * NN + nbase;
        float2 p0 = *reinterpret_cast<float2*>(&acc[0][j]);
        float2 p1 = *reinterpret_cast<float2*>(&acc[1][j]);
        *(float4*)op = make_float4(p0.x + bv, p0.y + bv, p1.x + bv, p1.y + bv);
    }
}

// ---------------- launch ----------------
extern "C" void kernel_launch(void* const* d_in, const int* in_sizes, int n_in,
                              void* d_out, int out_size) {
    const float* coords        = (const float*)d_in[0];   // (4,3,4096)
    const float* features      = (const float*)d_in[1];   // (4,64,4096)
    const float* kernel_points = (const float*)d_in[2];   // (15,3)
    const float* kernel_w      = (const float*)d_in[3];   // (15,64,128)
    const float* bias          = (const float*)d_in[4];   // (128,)
    float* out = (float*)d_out;                           // (4,128,4096)

    prep_coords_kernel<<<BB * NN / 256, 256>>>(coords);
    prep_feat_kernel<<<dim3(NN / 32, CIN / 32, BB), dim3(32, 8)>>>(features);
    knn_kernel<<<BB * NN / 32, 256>>>();
    agg_kernel<<<BB * NN, 64>>>(kernel_points);
    gemm_kernel<<<BB * NN / 64, 256>>>(kernel_w, bias, out);
}

// round 4
// speedup vs baseline: 2.7486x; 2.7486x over previous
#include <cuda_runtime.h>
#include <math_constants.h>

// Problem constants
#define BB   4
#define NN   4096
#define CIN  64
#define COUT 128
#define KP   15
#define KNNK 16
#define KDIM (KP * CIN)   // 960

// ---------------- device scratch (no cudaMalloc allowed) ----------------
__device__ float4 g_coordsT[BB * NN];                 // (x,y,z,|c|^2) point-major
__device__ float  g_featT[BB * NN * CIN];             // features point-major
__device__ int    g_nbr[BB * NN * KNNK];              // knn indices
__device__ float  g_agg[(size_t)BB * NN * KDIM];      // aggregated features (63 MB)

// f32x2 packed-fma helpers
__device__ __forceinline__ unsigned long long pack2(float x) {
    unsigned long long r;
    asm("mov.b64 %0, {%1, %1};" : "=l"(r) : "f"(x));
    return r;
}
__device__ __forceinline__ void fma2(unsigned long long& d, unsigned long long a, unsigned long long b) {
    asm("fma.rn.f32x2 %0, %1, %2, %0;" : "+l"(d) : "l"(a), "l"(b));
}

// ---------------- stage 0: merged prep (coords AoS + feature transpose) ----------------
// Blocks 0..63: coords (B,3,N) -> float4 (x,y,z,|c|^2).
// Blocks 64..1087: features (B,C,N) -> (B,N,C), 32x32 tiles.
__global__ __launch_bounds__(256) void prep_kernel(const float* __restrict__ coords,
                                                   const float* __restrict__ feats) {
    if (blockIdx.x < 64) {
        int i = blockIdx.x * 256 + threadIdx.x;      // 0..16383
        int b = i >> 12;
        int n = i & (NN - 1);
        const float* cb = coords + (size_t)b * 3 * NN;
        float x = cb[n], y = cb[NN + n], z = cb[2 * NN + n];
        g_coordsT[i] = make_float4(x, y, z, x * x + y * y + z * z);
    } else {
        __shared__ float tile[32][33];
        int idx = blockIdx.x - 64;                   // 0..1023
        int b   = idx >> 8;
        int rem = idx & 255;
        int n0  = (rem & 127) * 32;
        int c0  = (rem >> 7) * 32;
        int tx  = threadIdx.x & 31;
        int ty  = threadIdx.x >> 5;                  // 0..7
        const float* fb = feats + (size_t)b * CIN * NN;
        #pragma unroll
        for (int r = 0; r < 32; r += 8)
            tile[ty + r][tx] = fb[(size_t)(c0 + ty + r) * NN + n0 + tx];
        __syncthreads();
        float* ob = g_featT + (size_t)b * NN * CIN;
        #pragma unroll
        for (int r = 0; r < 32; r += 8)
            ob[(size_t)(n0 + ty + r) * CIN + c0 + tx] = tile[tx][ty + r];
    }
}

// ---------------- stage 1: KNN, warp-per-query, ballot-filtered top-16 ----------------
// The top-16 is distributed one entry per lane in lanes 0..15, sorted DESCENDING
// (lane 0 = current 16th-best = threshold). Lanes 16..31 hold -inf sentinels.
// Per 32-candidate batch: coalesced load + 3 FMA in the shifted metric
// d' = |c|^2 - 2 q.c (ordering == true d2) + one ballot. Rare survivors are
// serialized and inserted via a 2-shuffle sorted shift; inserting a
// non-qualifying d is a provable no-op, so the loop needs no rechecks.
__global__ __launch_bounds__(256) void knn_kernel() {
    int warp = threadIdx.x >> 5;
    int lane = threadIdx.x & 31;
    int q    = blockIdx.x * 8 + warp;
    int b    = q >> 12;
    int n    = q & (NN - 1);

    const float4* base = g_coordsT + (b << 12);
    float4 qc = __ldg(&base[n]);
    float qx2 = -2.0f * qc.x, qy2 = -2.0f * qc.y, qz2 = -2.0f * qc.z;

    float val = (lane < KNNK) ? CUDART_INF_F : -CUDART_INF_F;
    int   idx = -1;
    float thr = CUDART_INF_F;

    for (int jj = 0; jj < NN / 32; jj++) {
        int j = (jj << 5) + lane;
        float4 c = __ldg(&base[j]);
        float d = fmaf(c.x, qx2, fmaf(c.y, qy2, fmaf(c.z, qz2, c.w)));
        unsigned mask = __ballot_sync(0xffffffffu, (d < thr) && (j != n));
        if (mask) {
            do {
                int s = __ffs(mask) - 1;
                mask &= mask - 1;
                float ds = __shfl_sync(0xffffffffu, d, s);
                int   js = __shfl_sync(0xffffffffu, j, s);
                // sorted-shift insert: drop current max (lane 0), insert ds
                float nv = __shfl_down_sync(0xffffffffu, val, 1);
                int   ni = __shfl_down_sync(0xffffffffu, idx, 1);
                bool takeNext = (nv >= ds);
                bool takeD    = (val >= ds);
                val = takeNext ? nv : (takeD ? ds : val);
                idx = takeNext ? ni : (takeD ? js : idx);
            } while (mask);
            thr = __shfl_sync(0xffffffffu, val, 0);
        }
    }

    if (lane < KNNK)
        g_nbr[(size_t)q * KNNK + lane] = idx;
}

// ---------------- stage 2: influence + aggregation ----------------
__global__ void agg_kernel(const float* __restrict__ kpts) {
    __shared__ int   nbr[KNNK];
    __shared__ float diffs[KNNK][3];
    __shared__ float kps[KP * 3];
    __shared__ float infl[KNNK][KP];

    int m   = blockIdx.x;
    int b   = m >> 12;
    int tid = threadIdx.x;

    if (tid < KP * 3) kps[tid] = kpts[tid];
    if (tid < KNNK)   nbr[tid] = g_nbr[(size_t)m * KNNK + tid];
    __syncthreads();
    if (tid < KNNK) {
        float4 qv = g_coordsT[m];
        float4 c  = g_coordsT[(b << 12) + nbr[tid]];
        diffs[tid][0] = c.x - qv.x;
        diffs[tid][1] = c.y - qv.y;
        diffs[tid][2] = c.z - qv.z;
    }
    __syncthreads();
    for (int t = tid; t < KNNK * KP; t += 64) {
        int kk = t / KP, p = t % KP;
        float dx = diffs[kk][0] - kps[p * 3 + 0];
        float dy = diffs[kk][1] - kps[p * 3 + 1];
        float dz = diffs[kk][2] - kps[p * 3 + 2];
        float sq = dx * dx + dy * dy + dz * dz;
        infl[kk][p] = expf(-sq * 100.0f);   // 1/SIGMA^2
    }
    __syncthreads();

    float a[KP];
    #pragma unroll
    for (int p = 0; p < KP; p++) a[p] = 0.0f;

    for (int kk = 0; kk < KNNK; kk++) {
        float f = g_featT[((size_t)(b << 12) + nbr[kk]) * CIN + tid];
        #pragma unroll
        for (int p = 0; p < KP; p++)
            a[p] += infl[kk][p] * f;
    }
    float* outp = g_agg + (size_t)m * KDIM;
    #pragma unroll
    for (int p = 0; p < KP; p++)
        outp[p * CIN + tid] = a[p];
}

// ---------------- stage 3: SGEMM via fma.rn.f32x2, 128x128 tile ----------------
__global__ __launch_bounds__(256) void gemm_kernel(const float* __restrict__ W,
                                                   const float* __restrict__ bias,
                                                   float* __restrict__ out) {
    __shared__ float As[2][16][128];   // As[buf][k][m]
    __shared__ float Bs[2][16][128];   // Bs[buf][k][n]

    int m0  = blockIdx.x * 128;
    int tid = threadIdx.x;
    int tx  = tid & 15;                // n group (8 cols)
    int ty  = tid >> 4;                // m group (8 rows)

    unsigned long long acc[4][8];      // [m-pair][n]
    #pragma unroll
    for (int i = 0; i < 4; i++)
        #pragma unroll
        for (int j = 0; j < 8; j++) acc[i][j] = 0ULL;

    const float* Ab = g_agg + (size_t)m0 * KDIM;
    int arow  = tid >> 2;              // 0..63
    int acol4 = (tid & 3) * 4;         // 0,4,8,12

    float4 a_r[2], b_r[2];

    // prologue: load k-tile 0
    a_r[0] = *(const float4*)(Ab + (size_t)arow * KDIM + acol4);
    a_r[1] = *(const float4*)(Ab + (size_t)(arow + 64) * KDIM + acol4);
    {
        int l0 = tid, l1 = tid + 256;
        b_r[0] = *(const float4*)(W + (size_t)(l0 >> 5) * COUT + (l0 & 31) * 4);
        b_r[1] = *(const float4*)(W + (size_t)(l1 >> 5) * COUT + (l1 & 31) * 4);
    }
    {
        As[0][acol4 + 0][arow] = a_r[0].x; As[0][acol4 + 1][arow] = a_r[0].y;
        As[0][acol4 + 2][arow] = a_r[0].z; As[0][acol4 + 3][arow] = a_r[0].w;
        As[0][acol4 + 0][arow + 64] = a_r[1].x; As[0][acol4 + 1][arow + 64] = a_r[1].y;
        As[0][acol4 + 2][arow + 64] = a_r[1].z; As[0][acol4 + 3][arow + 64] = a_r[1].w;
        int l0 = tid, l1 = tid + 256;
        *(float4*)&Bs[0][l0 >> 5][(l0 & 31) * 4] = b_r[0];
        *(float4*)&Bs[0][l1 >> 5][(l1 & 31) * 4] = b_r[1];
    }
    __syncthreads();

    int buf = 0;
    const int NIT = KDIM / 16;   // 60
    for (int it = 0; it < NIT; it++) {
        if (it < NIT - 1) {
            int k0 = (it + 1) * 16;
            a_r[0] = *(const float4*)(Ab + (size_t)arow * KDIM + k0 + acol4);
            a_r[1] = *(const float4*)(Ab + (size_t)(arow + 64) * KDIM + k0 + acol4);
            int l0 = tid, l1 = tid + 256;
            b_r[0] = *(const float4*)(W + (size_t)(k0 + (l0 >> 5)) * COUT + (l0 & 31) * 4);
            b_r[1] = *(const float4*)(W + (size_t)(k0 + (l1 >> 5)) * COUT + (l1 & 31) * 4);
        }

        #pragma unroll
        for (int k = 0; k < 16; k++) {
            ulonglong2 A0 = *(const ulonglong2*)&As[buf][k][ty * 8];
            ulonglong2 A1 = *(const ulonglong2*)&As[buf][k][ty * 8 + 4];
            unsigned long long ap0 = A0.x, ap1 = A0.y, ap2 = A1.x, ap3 = A1.y;
            float4 b0 = *(const float4*)&Bs[buf][k][tx * 8];
            float4 b1 = *(const float4*)&Bs[buf][k][tx * 8 + 4];
            unsigned long long bp[8];
            bp[0] = pack2(b0.x); bp[1] = pack2(b0.y); bp[2] = pack2(b0.z); bp[3] = pack2(b0.w);
            bp[4] = pack2(b1.x); bp[5] = pack2(b1.y); bp[6] = pack2(b1.z); bp[7] = pack2(b1.w);
            #pragma unroll
            for (int j = 0; j < 8; j++) {
                fma2(acc[0][j], ap0, bp[j]);
                fma2(acc[1][j], ap1, bp[j]);
                fma2(acc[2][j], ap2, bp[j]);
                fma2(acc[3][j], ap3, bp[j]);
            }
        }

        if (it < NIT - 1) {
            buf ^= 1;
            As[buf][acol4 + 0][arow] = a_r[0].x; As[buf][acol4 + 1][arow] = a_r[0].y;
            As[buf][acol4 + 2][arow] = a_r[0].z; As[buf][acol4 + 3][arow] = a_r[0].w;
            As[buf][acol4 + 0][arow + 64] = a_r[1].x; As[buf][acol4 + 1][arow + 64] = a_r[1].y;
            As[buf][acol4 + 2][arow + 64] = a_r[1].z; As[buf][acol4 + 3][arow + 64] = a_r[1].w;
            int l0 = tid, l1 = tid + 256;
            *(float4*)&Bs[buf][l0 >> 5][(l0 & 31) * 4] = b_r[0];
            *(float4*)&Bs[buf][l1 >> 5][(l1 & 31) * 4] = b_r[1];
            __syncthreads();
        }
    }

    // epilogue: out is (B, C_out, N); m maps to n (point index)
    int b     = m0 >> 12;
    int nbase = (m0 & (NN - 1)) + ty * 8;
    #pragma unroll
    for (int j = 0; j < 8; j++) {
        int o = tx * 8 + j;
        float bv = __ldg(&bias[o]);
        float* op = out + ((size_t)b * COUT + o) * NN + nbase;
        float2 p0 = *reinterpret_cast<float2*>(&acc[0][j]);
        float2 p1 = *reinterpret_cast<float2*>(&acc[1][j]);
        float2 p2 = *reinterpret_cast<float2*>(&acc[2][j]);
        float2 p3 = *reinterpret_cast<float2*>(&acc[3][j]);
        float4 v0 = make_float4(p0.x + bv, p0.y + bv, p1.x + bv, p1.y + bv);
        float4 v1 = make_float4(p2.x + bv, p2.y + bv, p3.x + bv, p3.y + bv);
        *(float4*)(op)     = v0;
        *(float4*)(op + 4) = v1;
    }
}

// ---------------- launch ----------------
extern "C" void kernel_launch(void* const* d_in, const int* in_sizes, int n_in,
                              void* d_out, int out_size) {
    const float* coords        = (const float*)d_in[0];   // (4,3,4096)
    const float* features      = (const float*)d_in[1];   // (4,64,4096)
    const float* kernel_points = (const float*)d_in[2];   // (15,3)
    const float* kernel_w      = (const float*)d_in[3];   // (15,64,128)
    const float* bias          = (const float*)d_in[4];   // (128,)
    float* out = (float*)d_out;                           // (4,128,4096)

    prep_kernel<<<64 + BB * 256, 256>>>(coords, features);
    knn_kernel<<<BB * NN / 8, 256>>>();
    agg_kernel<<<BB * NN, 64>>>(kernel_points);
    gemm_kernel<<<BB * NN / 128, 256>>>(kernel_w, bias, out);
}

// round 6
// speedup vs baseline: 3.4024x; 1.2378x over previous
#include <cuda_runtime.h>
#include <cuda_bf16.h>
#include <math_constants.h>
#include <cstdint>

// Problem constants
#define BB   4
#define NN   4096
#define CIN  64
#define COUT 128
#define KP   15
#define KNNK 16
#define KDIM (KP * CIN)   // 960

// ---------------- device scratch ----------------
__device__ float4 g_coordsT[BB * NN];
__device__ float  g_featT[BB * NN * CIN];
__device__ int    g_nbr[BB * NN * KNNK];
__device__ __align__(16) __nv_bfloat16 g_aggh[(size_t)BB * NN * KDIM];  // A hi [m][k]
__device__ __align__(16) __nv_bfloat16 g_aggl[(size_t)BB * NN * KDIM];  // A lo
__device__ __align__(16) __nv_bfloat16 g_wh[(size_t)COUT * KDIM];       // W^T hi [n][k]
__device__ __align__(16) __nv_bfloat16 g_wl[(size_t)COUT * KDIM];       // W^T lo

// ---------------- stage 0: prep (coords AoS + feat transpose + W split/transpose) ----------------
__global__ __launch_bounds__(256) void prep_kernel(const float* __restrict__ coords,
                                                   const float* __restrict__ feats,
                                                   const float* __restrict__ W) {
    if (blockIdx.x < 64) {
        int i = blockIdx.x * 256 + threadIdx.x;
        int b = i >> 12;
        int n = i & (NN - 1);
        const float* cb = coords + (size_t)b * 3 * NN;
        float x = cb[n], y = cb[NN + n], z = cb[2 * NN + n];
        g_coordsT[i] = make_float4(x, y, z, x * x + y * y + z * z);
    } else if (blockIdx.x < 64 + 1024) {
        __shared__ float tile[32][33];
        int idx = blockIdx.x - 64;
        int b   = idx >> 8;
        int rem = idx & 255;
        int n0  = (rem & 127) * 32;
        int c0  = (rem >> 7) * 32;
        int tx  = threadIdx.x & 31;
        int ty  = threadIdx.x >> 5;
        const float* fb = feats + (size_t)b * CIN * NN;
        #pragma unroll
        for (int r = 0; r < 32; r += 8)
            tile[ty + r][tx] = fb[(size_t)(c0 + ty + r) * NN + n0 + tx];
        __syncthreads();
        float* ob = g_featT + (size_t)b * NN * CIN;
        #pragma unroll
        for (int r = 0; r < 32; r += 8)
            ob[(size_t)(n0 + ty + r) * CIN + c0 + tx] = tile[tx][ty + r];
    } else {
        // W (960,128) -> W^T hi/lo [n][k]
        int idx = (blockIdx.x - 1088) * 256 + threadIdx.x;   // 0..122879
        int n = idx / KDIM;
        int k = idx - n * KDIM;
        float w = W[(size_t)k * COUT + n];
        __nv_bfloat16 h = __float2bfloat16(w);
        __nv_bfloat16 l = __float2bfloat16(w - __bfloat162float(h));
        g_wh[(size_t)n * KDIM + k] = h;
        g_wl[(size_t)n * KDIM + k] = l;
    }
}

// ---------------- stage 1: KNN (warp-per-query, ballot-filtered) ----------------
__global__ __launch_bounds__(256) void knn_kernel() {
    int warp = threadIdx.x >> 5;
    int lane = threadIdx.x & 31;
    int q    = blockIdx.x * 8 + warp;
    int b    = q >> 12;
    int n    = q & (NN - 1);

    const float4* base = g_coordsT + (b << 12);
    float4 qc = __ldg(&base[n]);
    float qx2 = -2.0f * qc.x, qy2 = -2.0f * qc.y, qz2 = -2.0f * qc.z;

    float val = (lane < KNNK) ? CUDART_INF_F : -CUDART_INF_F;
    int   idx = -1;
    float thr = CUDART_INF_F;

    for (int jj = 0; jj < NN / 32; jj++) {
        int j = (jj << 5) + lane;
        float4 c = __ldg(&base[j]);
        float d = fmaf(c.x, qx2, fmaf(c.y, qy2, fmaf(c.z, qz2, c.w)));
        unsigned mask = __ballot_sync(0xffffffffu, (d < thr) && (j != n));
        if (mask) {
            do {
                int s = __ffs(mask) - 1;
                mask &= mask - 1;
                float ds = __shfl_sync(0xffffffffu, d, s);
                int   js = __shfl_sync(0xffffffffu, j, s);
                float nv = __shfl_down_sync(0xffffffffu, val, 1);
                int   ni = __shfl_down_sync(0xffffffffu, idx, 1);
                bool takeNext = (nv >= ds);
                bool takeD    = (val >= ds);
                val = takeNext ? nv : (takeD ? ds : val);
                idx = takeNext ? ni : (takeD ? js : idx);
            } while (mask);
            thr = __shfl_sync(0xffffffffu, val, 0);
        }
    }

    if (lane < KNNK)
        g_nbr[(size_t)q * KNNK + lane] = idx;
}

// ---------------- stage 2: influence + aggregation -> bf16 hi/lo ----------------
__global__ void agg_kernel(const float* __restrict__ kpts) {
    __shared__ int   nbr[KNNK];
    __shared__ float diffs[KNNK][3];
    __shared__ float kps[KP * 3];
    __shared__ float infl[KNNK][KP];

    int m   = blockIdx.x;
    int b   = m >> 12;
    int tid = threadIdx.x;

    if (tid < KP * 3) kps[tid] = kpts[tid];
    if (tid < KNNK)   nbr[tid] = g_nbr[(size_t)m * KNNK + tid];
    __syncthreads();
    if (tid < KNNK) {
        float4 qv = g_coordsT[m];
        float4 c  = g_coordsT[(b << 12) + nbr[tid]];
        diffs[tid][0] = c.x - qv.x;
        diffs[tid][1] = c.y - qv.y;
        diffs[tid][2] = c.z - qv.z;
    }
    __syncthreads();
    for (int t = tid; t < KNNK * KP; t += 64) {
        int kk = t / KP, p = t % KP;
        float dx = diffs[kk][0] - kps[p * 3 + 0];
        float dy = diffs[kk][1] - kps[p * 3 + 1];
        float dz = diffs[kk][2] - kps[p * 3 + 2];
        float sq = dx * dx + dy * dy + dz * dz;
        infl[kk][p] = expf(-sq * 100.0f);
    }
    __syncthreads();

    float a[KP];
    #pragma unroll
    for (int p = 0; p < KP; p++) a[p] = 0.0f;

    for (int kk = 0; kk < KNNK; kk++) {
        float f = g_featT[((size_t)(b << 12) + nbr[kk]) * CIN + tid];
        #pragma unroll
        for (int p = 0; p < KP; p++)
            a[p] += infl[kk][p] * f;
    }
    size_t rb = (size_t)m * KDIM + tid;
    #pragma unroll
    for (int p = 0; p < KP; p++) {
        float v = a[p];
        __nv_bfloat16 h = __float2bfloat16(v);
        __nv_bfloat16 l = __float2bfloat16(v - __bfloat162float(h));
        g_aggh[rb + p * CIN] = h;
        g_aggl[rb + p * CIN] = l;
    }
}

// ---------------- stage 3: mma.sync bf16 3-pass GEMM ----------------
// C(16384x128) = A(16384x960) @ W^T(128x960)^T with A,W split hi/lo.
// CTA: 128x128 tile, 8 warps (2m x 4n), warp tile 64x32.
// mma.sync.aligned.m16n8k16.row.col.f32.bf16.bf16.f32 fragments loaded via
// explicit LDS (conflict-free with row stride 72 bf16).
#define KCH     64
#define NCHUNK  (KDIM / KCH)              // 15
#define ASTRIDE 72                        // bf16 elems per smem row (pad 64->72)
#define TILE_B  (128 * ASTRIDE * 2)       // 18432 bytes
#define BUF_B   (4 * TILE_B)              // Ah|Al|Bh|Bl = 73728
#define SMEM_DYN (2 * BUF_B)              // 147456 (double buffer)

__device__ __forceinline__ void mma16816(float* c, const uint32_t* a, const uint32_t* b) {
    asm volatile(
        "mma.sync.aligned.m16n8k16.row.col.f32.bf16.bf16.f32 "
        "{%0,%1,%2,%3}, {%4,%5,%6,%7}, {%8,%9}, {%0,%1,%2,%3};"
        : "+f"(c[0]), "+f"(c[1]), "+f"(c[2]), "+f"(c[3])
        : "r"(a[0]), "r"(a[1]), "r"(a[2]), "r"(a[3]), "r"(b[0]), "r"(b[1]));
}

__global__ __launch_bounds__(256, 1) void gemm_kernel(const float* __restrict__ bias,
                                                      float* __restrict__ out) {
    extern __shared__ __align__(16) char smem[];
    int tid  = threadIdx.x;
    int warp = tid >> 5;
    int lane = tid & 31;
    int wm   = warp >> 2;       // 0..1
    int wn   = warp & 3;        // 0..3
    int g    = lane >> 2;       // groupID 0..7
    int tig  = lane & 3;        // thread in group
    int m0   = blockIdx.x * 128;

    float acc[4][4][4];
    #pragma unroll
    for (int i = 0; i < 4; i++)
        #pragma unroll
        for (int j = 0; j < 4; j++)
            #pragma unroll
            for (int c = 0; c < 4; c++) acc[i][j][c] = 0.0f;

    const char* srcs[4] = {
        (const char*)g_aggh + (size_t)m0 * (KDIM * 2),
        (const char*)g_aggl + (size_t)m0 * (KDIM * 2),
        (const char*)g_wh,
        (const char*)g_wl };

    // chunk loader: 4 tiles x (128 rows x 8 seg16B) = 4096 uint4, 16/thread
    auto load_chunk = [&](int ch, int bufsel) {
        char* dst0 = smem + bufsel * BUF_B;
        size_t koff = (size_t)ch * (KCH * 2);
        #pragma unroll
        for (int i = 0; i < 16; i++) {
            int gi   = tid + 256 * i;
            int tile = gi >> 10;
            int wi   = gi & 1023;
            int r    = wi >> 3;
            int s    = wi & 7;
            uint4 v = *(const uint4*)(srcs[tile] + (size_t)r * (KDIM * 2) + koff + s * 16);
            *(uint4*)(dst0 + tile * TILE_B + r * (ASTRIDE * 2) + s * 16) = v;
        }
    };

    load_chunk(0, 0);
    __syncthreads();

    for (int ch = 0; ch < NCHUNK; ch++) {
        int bufsel = ch & 1;
        if (ch + 1 < NCHUNK) load_chunk(ch + 1, bufsel ^ 1);

        const uint32_t* Ah = (const uint32_t*)(smem + bufsel * BUF_B);
        const uint32_t* Al = (const uint32_t*)(smem + bufsel * BUF_B + TILE_B);
        const uint32_t* Bh = (const uint32_t*)(smem + bufsel * BUF_B + 2 * TILE_B);
        const uint32_t* Bl = (const uint32_t*)(smem + bufsel * BUF_B + 3 * TILE_B);

        #pragma unroll
        for (int ks = 0; ks < KCH / 16; ks++) {
            int kb = ks * 8 + tig;   // uint32 (bf16-pair) index within row
            uint32_t ah[4][4], al[4][4], bh[4][2], bl[4][2];
            #pragma unroll
            for (int mt = 0; mt < 4; mt++) {
                int r0 = (wm * 64 + mt * 16 + g) * (ASTRIDE / 2);
                int r1 = r0 + 8 * (ASTRIDE / 2);
                ah[mt][0] = Ah[r0 + kb];     ah[mt][1] = Ah[r1 + kb];
                ah[mt][2] = Ah[r0 + kb + 4]; ah[mt][3] = Ah[r1 + kb + 4];
                al[mt][0] = Al[r0 + kb];     al[mt][1] = Al[r1 + kb];
                al[mt][2] = Al[r0 + kb + 4]; al[mt][3] = Al[r1 + kb + 4];
            }
            #pragma unroll
            for (int nt = 0; nt < 4; nt++) {
                int r0 = (wn * 32 + nt * 8 + g) * (ASTRIDE / 2);
                bh[nt][0] = Bh[r0 + kb]; bh[nt][1] = Bh[r0 + kb + 4];
                bl[nt][0] = Bl[r0 + kb]; bl[nt][1] = Bl[r0 + kb + 4];
            }
            #pragma unroll
            for (int mt = 0; mt < 4; mt++)
                #pragma unroll
                for (int nt = 0; nt < 4; nt++) {
                    mma16816(acc[mt][nt], ah[mt], bh[nt]);
                    mma16816(acc[mt][nt], ah[mt], bl[nt]);
                    mma16816(acc[mt][nt], al[mt], bh[nt]);
                }
        }
        __syncthreads();
    }

    // epilogue: stage to smem as [o][m] (stride 132, conflict-free), then
    // coalesced float4 STG into out (B, C_out, N) with bias.
    float* so = (float*)smem;
    #pragma unroll
    for (int mt = 0; mt < 4; mt++)
        #pragma unroll
        for (int nt = 0; nt < 4; nt++) {
            int m = wm * 64 + mt * 16 + g;
            int o = wn * 32 + nt * 8 + tig * 2;
            so[o * 132 + m]             = acc[mt][nt][0];
            so[(o + 1) * 132 + m]       = acc[mt][nt][1];
            so[o * 132 + m + 8]         = acc[mt][nt][2];
            so[(o + 1) * 132 + m + 8]   = acc[mt][nt][3];
        }
    __syncthreads();

    int b    = m0 >> 12;
    int nptb = m0 & (NN - 1);
    #pragma unroll
    for (int i = 0; i < 16; i++) {
        int idx = tid + i * 256;       // 0..4095
        int o   = idx >> 5;
        int m4  = (idx & 31) * 4;
        float bv = __ldg(&bias[o]);
        float4 v = *(float4*)&so[o * 132 + m4];
        v.x += bv; v.y += bv; v.z += bv; v.w += bv;
        *(float4*)(out + ((size_t)b * COUT + o) * NN + nptb + m4) = v;
    }
}

// ---------------- launch ----------------
extern "C" void kernel_launch(void* const* d_in, const int* in_sizes, int n_in,
                              void* d_out, int out_size) {
    const float* coords        = (const float*)d_in[0];   // (4,3,4096)
    const float* features      = (const float*)d_in[1];   // (4,64,4096)
    const float* kernel_points = (const float*)d_in[2];   // (15,3)
    const float* kernel_w      = (const float*)d_in[3];   // (15,64,128)
    const float* bias          = (const float*)d_in[4];   // (128,)
    float* out = (float*)d_out;                           // (4,128,4096)

    static bool attr_set = false;
    if (!attr_set) {
        cudaFuncSetAttribute(gemm_kernel, cudaFuncAttributeMaxDynamicSharedMemorySize, SMEM_DYN);
        attr_set = true;
    }

    prep_kernel<<<64 + 1024 + 480, 256>>>(coords, features, kernel_w);
    knn_kernel<<<BB * NN / 8, 256>>>();
    agg_kernel<<<BB * NN, 64>>>(kernel_points);
    gemm_kernel<<<BB * NN / 128, 256, SMEM_DYN>>>(bias, out);
}

// round 10
// speedup vs baseline: 3.5038x; 1.0298x over previous
#include <cuda_runtime.h>
#include <cuda_bf16.h>
#include <math_constants.h>
#include <cstdint>

// Problem constants
#define BB   4
#define NN   4096
#define CIN  64
#define COUT 128
#define KP   15
#define KNNK 16
#define KDIM (KP * CIN)   // 960

// ---------------- device scratch ----------------
__device__ float4 g_coordsT[BB * NN];
__device__ float  g_featT[BB * NN * CIN];
__device__ int    g_nbr[BB * NN * KNNK];
__device__ __align__(16) __nv_bfloat16 g_aggh[(size_t)BB * NN * KDIM];  // A hi [m][k]
__device__ __align__(16) __nv_bfloat16 g_aggl[(size_t)BB * NN * KDIM];  // A lo
__device__ __align__(16) __nv_bfloat16 g_wh[(size_t)COUT * KDIM];       // W^T hi [n][k]
__device__ __align__(16) __nv_bfloat16 g_wl[(size_t)COUT * KDIM];       // W^T lo

// ---------------- stage 0: prep ----------------
__global__ __launch_bounds__(256) void prep_kernel(const float* __restrict__ coords,
                                                   const float* __restrict__ feats,
                                                   const float* __restrict__ W) {
    if (blockIdx.x < 64) {
        int i = blockIdx.x * 256 + threadIdx.x;
        int b = i >> 12;
        int n = i & (NN - 1);
        const float* cb = coords + (size_t)b * 3 * NN;
        float x = cb[n], y = cb[NN + n], z = cb[2 * NN + n];
        g_coordsT[i] = make_float4(x, y, z, x * x + y * y + z * z);
    } else if (blockIdx.x < 64 + 1024) {
        __shared__ float tile[32][33];
        int idx = blockIdx.x - 64;
        int b   = idx >> 8;
        int rem = idx & 255;
        int n0  = (rem & 127) * 32;
        int c0  = (rem >> 7) * 32;
        int tx  = threadIdx.x & 31;
        int ty  = threadIdx.x >> 5;
        const float* fb = feats + (size_t)b * CIN * NN;
        #pragma unroll
        for (int r = 0; r < 32; r += 8)
            tile[ty + r][tx] = fb[(size_t)(c0 + ty + r) * NN + n0 + tx];
        __syncthreads();
        float* ob = g_featT + (size_t)b * NN * CIN;
        #pragma unroll
        for (int r = 0; r < 32; r += 8)
            ob[(size_t)(n0 + ty + r) * CIN + c0 + tx] = tile[tx][ty + r];
    } else {
        int idx = (blockIdx.x - 1088) * 256 + threadIdx.x;
        int n = idx / KDIM;
        int k = idx - n * KDIM;
        float w = W[(size_t)k * COUT + n];
        __nv_bfloat16 h = __float2bfloat16(w);
        __nv_bfloat16 l = __float2bfloat16(w - __bfloat162float(h));
        g_wh[(size_t)n * KDIM + k] = h;
        g_wl[(size_t)n * KDIM + k] = l;
    }
}

// ---------------- stage 1: KNN, 2 queries per warp ----------------
// Lanes 0..15 hold qA's top-16 (sorted descending, seg-lane 0 = threshold),
// lanes 16..31 hold qB's. Each candidate load (16B/lane) serves BOTH queries,
// halving L1 traffic. Inserts use width-16 shfl segments with a -inf sentinel
// forced at segment-lane 15.
__global__ __launch_bounds__(256) void knn_kernel() {
    int warp = threadIdx.x >> 5;
    int lane = threadIdx.x & 31;
    int seg  = lane >> 4;               // 0 -> qA, 1 -> qB
    int sl   = lane & 15;
    int pair = blockIdx.x * 8 + warp;   // 8192 pairs
    int q0   = pair * 2;
    int b    = q0 >> 12;
    int nA   = q0 & (NN - 1);
    int nB   = nA + 1;

    const float4* base = g_coordsT + (b << 12);
    float4 qa = __ldg(&base[nA]);
    float4 qb = __ldg(&base[nB]);
    float ax = -2.0f * qa.x, ay = -2.0f * qa.y, az = -2.0f * qa.z;
    float bx = -2.0f * qb.x, by = -2.0f * qb.y, bz = -2.0f * qb.z;

    float val = CUDART_INF_F;
    int   idx = -1;
    float thrA = CUDART_INF_F, thrB = CUDART_INF_F;

    for (int jj = 0; jj < NN / 32; jj++) {
        int j = (jj << 5) + lane;
        float4 c = __ldg(&base[j]);
        float dA = fmaf(c.x, ax, fmaf(c.y, ay, fmaf(c.z, az, c.w)));
        float dB = fmaf(c.x, bx, fmaf(c.y, by, fmaf(c.z, bz, c.w)));
        unsigned mA = __ballot_sync(0xffffffffu, (dA < thrA) && (j != nA));
        unsigned mB = __ballot_sync(0xffffffffu, (dB < thrB) && (j != nB));
        if (mA) {
            do {
                int s = __ffs(mA) - 1;
                mA &= mA - 1;
                float ds = __shfl_sync(0xffffffffu, dA, s);
                int   js = (jj << 5) + s;
                float nv = __shfl_down_sync(0xffffffffu, val, 1, 16);
                int   ni = __shfl_down_sync(0xffffffffu, idx, 1, 16);
                if (sl == 15) { nv = -CUDART_INF_F; ni = -1; }
                bool takeNext = (nv >= ds);
                bool takeD    = (val >= ds);
                if (seg == 0) {
                    val = takeNext ? nv : (takeD ? ds : val);
                    idx = takeNext ? ni : (takeD ? js : idx);
                }
            } while (mA);
            thrA = __shfl_sync(0xffffffffu, val, 0);
        }
        if (mB) {
            do {
                int s = __ffs(mB) - 1;
                mB &= mB - 1;
                float ds = __shfl_sync(0xffffffffu, dB, s);
                int   js = (jj << 5) + s;
                float nv = __shfl_down_sync(0xffffffffu, val, 1, 16);
                int   ni = __shfl_down_sync(0xffffffffu, idx, 1, 16);
                if (sl == 15) { nv = -CUDART_INF_F; ni = -1; }
                bool takeNext = (nv >= ds);
                bool takeD    = (val >= ds);
                if (seg == 1) {
                    val = takeNext ? nv : (takeD ? ds : val);
                    idx = takeNext ? ni : (takeD ? js : idx);
                }
            } while (mB);
            thrB = __shfl_sync(0xffffffffu, val, 16);
        }
    }

    int q = q0 + seg;
    g_nbr[(size_t)q * KNNK + sl] = idx;
}

// ---------------- stage 2: influence + aggregation -> bf16 hi/lo ----------------
__global__ void agg_kernel(const float* __restrict__ kpts) {
    __shared__ int   nbr[KNNK];
    __shared__ float diffs[KNNK][3];
    __shared__ float kps[KP * 3];
    __shared__ float infl[KNNK][KP];

    int m   = blockIdx.x;
    int b   = m >> 12;
    int tid = threadIdx.x;

    if (tid < KP * 3) kps[tid] = kpts[tid];
    if (tid < KNNK)   nbr[tid] = g_nbr[(size_t)m * KNNK + tid];
    __syncthreads();
    if (tid < KNNK) {
        float4 qv = g_coordsT[m];
        float4 c  = g_coordsT[(b << 12) + nbr[tid]];
        diffs[tid][0] = c.x - qv.x;
        diffs[tid][1] = c.y - qv.y;
        diffs[tid][2] = c.z - qv.z;
    }
    __syncthreads();
    for (int t = tid; t < KNNK * KP; t += 64) {
        int kk = t / KP, p = t % KP;
        float dx = diffs[kk][0] - kps[p * 3 + 0];
        float dy = diffs[kk][1] - kps[p * 3 + 1];
        float dz = diffs[kk][2] - kps[p * 3 + 2];
        float sq = dx * dx + dy * dy + dz * dz;
        infl[kk][p] = expf(-sq * 100.0f);
    }
    __syncthreads();

    float a[KP];
    #pragma unroll
    for (int p = 0; p < KP; p++) a[p] = 0.0f;

    for (int kk = 0; kk < KNNK; kk++) {
        float f = g_featT[((size_t)(b << 12) + nbr[kk]) * CIN + tid];
        #pragma unroll
        for (int p = 0; p < KP; p++)
            a[p] += infl[kk][p] * f;
    }
    size_t rb = (size_t)m * KDIM + tid;
    #pragma unroll
    for (int p = 0; p < KP; p++) {
        float v = a[p];
        __nv_bfloat16 h = __float2bfloat16(v);
        __nv_bfloat16 l = __float2bfloat16(v - __bfloat162float(h));
        g_aggh[rb + p * CIN] = h;
        g_aggl[rb + p * CIN] = l;
    }
}

// ---------------- stage 3: mma.sync bf16 3-pass GEMM with fragment pipeline ----------------
#define KCH     64
#define NCHUNK  (KDIM / KCH)              // 15
#define ASTRIDE 72
#define TILE_B  (128 * ASTRIDE * 2)       // 18432
#define BUF_B   (4 * TILE_B)              // 73728
#define SMEM_DYN (2 * BUF_B)              // 147456

__device__ __forceinline__ void mma16816(float* c, const uint32_t* a, const uint32_t* b) {
    asm volatile(
        "mma.sync.aligned.m16n8k16.row.col.f32.bf16.bf16.f32 "
        "{%0,%1,%2,%3}, {%4,%5,%6,%7}, {%8,%9}, {%0,%1,%2,%3};"
        : "+f"(c[0]), "+f"(c[1]), "+f"(c[2]), "+f"(c[3])
        : "r"(a[0]), "r"(a[1]), "r"(a[2]), "r"(a[3]), "r"(b[0]), "r"(b[1]));
}

__global__ __launch_bounds__(256, 1) void gemm_kernel(const float* __restrict__ bias,
                                                      float* __restrict__ out) {
    extern __shared__ __align__(16) char smem[];
    int tid  = threadIdx.x;
    int warp = tid >> 5;
    int lane = tid & 31;
    int wm   = warp >> 2;
    int wn   = warp & 3;
    int g    = lane >> 2;
    int tig  = lane & 3;
    int m0   = blockIdx.x * 128;

    float acc[4][4][4];
    #pragma unroll
    for (int i = 0; i < 4; i++)
        #pragma unroll
        for (int j = 0; j < 4; j++)
            #pragma unroll
            for (int c = 0; c < 4; c++) acc[i][j][c] = 0.0f;

    const char* srcs[4] = {
        (const char*)g_aggh + (size_t)m0 * (KDIM * 2),
        (const char*)g_aggl + (size_t)m0 * (KDIM * 2),
        (const char*)g_wh,
        (const char*)g_wl };

    auto load_chunk = [&](int ch, int bufsel) {
        char* dst0 = smem + bufsel * BUF_B;
        size_t koff = (size_t)ch * (KCH * 2);
        #pragma unroll
        for (int i = 0; i < 16; i++) {
            int gi   = tid + 256 * i;
            int tile = gi >> 10;
            int wi   = gi & 1023;
            int r    = wi >> 3;
            int s    = wi & 7;
            uint4 v = *(const uint4*)(srcs[tile] + (size_t)r * (KDIM * 2) + koff + s * 16);
            *(uint4*)(dst0 + tile * TILE_B + r * (ASTRIDE * 2) + s * 16) = v;
        }
    };

    // fragment double-buffer
    uint32_t ah[2][4][4], al[2][4][4], bh[2][4][2], bl[2][4][2];

    auto load_frags = [&](int pb, int bufsel, int ks) {
        const uint32_t* Ah = (const uint32_t*)(smem + bufsel * BUF_B);
        const uint32_t* Al = (const uint32_t*)(smem + bufsel * BUF_B + TILE_B);
        const uint32_t* Bh = (const uint32_t*)(smem + bufsel * BUF_B + 2 * TILE_B);
        const uint32_t* Bl = (const uint32_t*)(smem + bufsel * BUF_B + 3 * TILE_B);
        int kb = ks * 8 + tig;
        #pragma unroll
        for (int mt = 0; mt < 4; mt++) {
            int r0 = (wm * 64 + mt * 16 + g) * (ASTRIDE / 2);
            int r1 = r0 + 8 * (ASTRIDE / 2);
            ah[pb][mt][0] = Ah[r0 + kb];     ah[pb][mt][1] = Ah[r1 + kb];
            ah[pb][mt][2] = Ah[r0 + kb + 4]; ah[pb][mt][3] = Ah[r1 + kb + 4];
            al[pb][mt][0] = Al[r0 + kb];     al[pb][mt][1] = Al[r1 + kb];
            al[pb][mt][2] = Al[r0 + kb + 4]; al[pb][mt][3] = Al[r1 + kb + 4];
        }
        #pragma unroll
        for (int nt = 0; nt < 4; nt++) {
            int r0 = (wn * 32 + nt * 8 + g) * (ASTRIDE / 2);
            bh[pb][nt][0] = Bh[r0 + kb]; bh[pb][nt][1] = Bh[r0 + kb + 4];
            bl[pb][nt][0] = Bl[r0 + kb]; bl[pb][nt][1] = Bl[r0 + kb + 4];
        }
    };

    load_chunk(0, 0);
    __syncthreads();

    for (int ch = 0; ch < NCHUNK; ch++) {
        int bufsel = ch & 1;
        load_frags(0, bufsel, 0);
        if (ch + 1 < NCHUNK) load_chunk(ch + 1, bufsel ^ 1);

        #pragma unroll
        for (int ks = 0; ks < KCH / 16; ks++) {
            int pf = ks & 1;
            if (ks < KCH / 16 - 1) load_frags(pf ^ 1, bufsel, ks + 1);
            #pragma unroll
            for (int mt = 0; mt < 4; mt++)
                #pragma unroll
                for (int nt = 0; nt < 4; nt++) {
                    mma16816(acc[mt][nt], ah[pf][mt], bh[pf][nt]);
                    mma16816(acc[mt][nt], ah[pf][mt], bl[pf][nt]);
                    mma16816(acc[mt][nt], al[pf][mt], bh[pf][nt]);
                }
        }
        __syncthreads();
    }

    // epilogue: stage [o][m] in smem (stride 132), coalesced float4 STG
    float* so = (float*)smem;
    #pragma unroll
    for (int mt = 0; mt < 4; mt++)
        #pragma unroll
        for (int nt = 0; nt < 4; nt++) {
            int m = wm * 64 + mt * 16 + g;
            int o = wn * 32 + nt * 8 + tig * 2;
            so[o * 132 + m]           = acc[mt][nt][0];
            so[(o + 1) * 132 + m]     = acc[mt][nt][1];
            so[o * 132 + m + 8]       = acc[mt][nt][2];
            so[(o + 1) * 132 + m + 8] = acc[mt][nt][3];
        }
    __syncthreads();

    int b    = m0 >> 12;
    int nptb = m0 & (NN - 1);
    #pragma unroll
    for (int i = 0; i < 16; i++) {
        int idx = tid + i * 256;
        int o   = idx >> 5;
        int m4  = (idx & 31) * 4;
        float bv = __ldg(&bias[o]);
        float4 v = *(float4*)&so[o * 132 + m4];
        v.x += bv; v.y += bv; v.z += bv; v.w += bv;
        *(float4*)(out + ((size_t)b * COUT + o) * NN + nptb + m4) = v;
    }
}

// ---------------- launch ----------------
extern "C" void kernel_launch(void* const* d_in, const int* in_sizes, int n_in,
                              void* d_out, int out_size) {
    const float* coords        = (const float*)d_in[0];
    const float* features      = (const float*)d_in[1];
    const float* kernel_points = (const float*)d_in[2];
    const float* kernel_w      = (const float*)d_in[3];
    const float* bias          = (const float*)d_in[4];
    float* out = (float*)d_out;

    static bool attr_set = false;
    if (!attr_set) {
        cudaFuncSetAttribute(gemm_kernel, cudaFuncAttributeMaxDynamicSharedMemorySize, SMEM_DYN);
        attr_set = true;
    }

    prep_kernel<<<64 + 1024 + 480, 256>>>(coords, features, kernel_w);
    knn_kernel<<<BB * NN / 16, 256>>>();
    agg_kernel<<<BB * NN, 64>>>(kernel_points);
    gemm_kernel<<<BB * NN / 128, 256, SMEM_DYN>>>(bias, out);
}

// round 11
// speedup vs baseline: 3.5096x; 1.0017x over previous
#include <cuda_runtime.h>
#include <cuda_bf16.h>
#include <math_constants.h>
#include <cstdint>

// Problem constants
#define BB   4
#define NN   4096
#define CIN  64
#define COUT 128
#define KP   15
#define KNNK 16
#define KDIM (KP * CIN)   // 960

// ---------------- device scratch ----------------
__device__ float4 g_coordsT[BB * NN];
__device__ float  g_featT[BB * NN * CIN];
__device__ int    g_nbr[BB * NN * KNNK];
__device__ __align__(16) __nv_bfloat16 g_aggh[(size_t)BB * NN * KDIM];  // A hi [m][k]
__device__ __align__(16) __nv_bfloat16 g_aggl[(size_t)BB * NN * KDIM];  // A lo
__device__ __align__(16) __nv_bfloat16 g_wh[(size_t)COUT * KDIM];       // W^T hi [n][k]
__device__ __align__(16) __nv_bfloat16 g_wl[(size_t)COUT * KDIM];       // W^T lo

// ---------------- stage 0: prep ----------------
__global__ __launch_bounds__(256) void prep_kernel(const float* __restrict__ coords,
                                                   const float* __restrict__ feats,
                                                   const float* __restrict__ W) {
    if (blockIdx.x < 64) {
        int i = blockIdx.x * 256 + threadIdx.x;
        int b = i >> 12;
        int n = i & (NN - 1);
        const float* cb = coords + (size_t)b * 3 * NN;
        float x = cb[n], y = cb[NN + n], z = cb[2 * NN + n];
        g_coordsT[i] = make_float4(x, y, z, x * x + y * y + z * z);
    } else if (blockIdx.x < 64 + 1024) {
        __shared__ float tile[32][33];
        int idx = blockIdx.x - 64;
        int b   = idx >> 8;
        int rem = idx & 255;
        int n0  = (rem & 127) * 32;
        int c0  = (rem >> 7) * 32;
        int tx  = threadIdx.x & 31;
        int ty  = threadIdx.x >> 5;
        const float* fb = feats + (size_t)b * CIN * NN;
        #pragma unroll
        for (int r = 0; r < 32; r += 8)
            tile[ty + r][tx] = fb[(size_t)(c0 + ty + r) * NN + n0 + tx];
        __syncthreads();
        float* ob = g_featT + (size_t)b * NN * CIN;
        #pragma unroll
        for (int r = 0; r < 32; r += 8)
            ob[(size_t)(n0 + ty + r) * CIN + c0 + tx] = tile[tx][ty + r];
    } else {
        int idx = (blockIdx.x - 1088) * 256 + threadIdx.x;
        int n = idx / KDIM;
        int k = idx - n * KDIM;
        float w = W[(size_t)k * COUT + n];
        __nv_bfloat16 h = __float2bfloat16(w);
        __nv_bfloat16 l = __float2bfloat16(w - __bfloat162float(h));
        g_wh[(size_t)n * KDIM + k] = h;
        g_wl[(size_t)n * KDIM + k] = l;
    }
}

// ---------------- stage 1: KNN, 2 queries per warp ----------------
// Lanes 0..15 hold qA's top-16 (sorted descending, seg-lane 0 = threshold),
// lanes 16..31 hold qB's. Each candidate load (16B/lane) serves BOTH queries,
// halving L1 traffic. Inserts use width-16 shfl segments with a -inf sentinel
// forced at segment-lane 15.
__global__ __launch_bounds__(256) void knn_kernel() {
    int warp = threadIdx.x >> 5;
    int lane = threadIdx.x & 31;
    int seg  = lane >> 4;               // 0 -> qA, 1 -> qB
    int sl   = lane & 15;
    int pair = blockIdx.x * 8 + warp;   // 8192 pairs
    int q0   = pair * 2;
    int b    = q0 >> 12;
    int nA   = q0 & (NN - 1);
    int nB   = nA + 1;

    const float4* base = g_coordsT + (b << 12);
    float4 qa = __ldg(&base[nA]);
    float4 qb = __ldg(&base[nB]);
    float ax = -2.0f * qa.x, ay = -2.0f * qa.y, az = -2.0f * qa.z;
    float bx = -2.0f * qb.x, by = -2.0f * qb.y, bz = -2.0f * qb.z;

    float val = CUDART_INF_F;
    int   idx = -1;
    float thrA = CUDART_INF_F, thrB = CUDART_INF_F;

    for (int jj = 0; jj < NN / 32; jj++) {
        int j = (jj << 5) + lane;
        float4 c = __ldg(&base[j]);
        float dA = fmaf(c.x, ax, fmaf(c.y, ay, fmaf(c.z, az, c.w)));
        float dB = fmaf(c.x, bx, fmaf(c.y, by, fmaf(c.z, bz, c.w)));
        unsigned mA = __ballot_sync(0xffffffffu, (dA < thrA) && (j != nA));
        unsigned mB = __ballot_sync(0xffffffffu, (dB < thrB) && (j != nB));
        if (mA) {
            do {
                int s = __ffs(mA) - 1;
                mA &= mA - 1;
                float ds = __shfl_sync(0xffffffffu, dA, s);
                int   js = (jj << 5) + s;
                float nv = __shfl_down_sync(0xffffffffu, val, 1, 16);
                int   ni = __shfl_down_sync(0xffffffffu, idx, 1, 16);
                if (sl == 15) { nv = -CUDART_INF_F; ni = -1; }
                bool takeNext = (nv >= ds);
                bool takeD    = (val >= ds);
                if (seg == 0) {
                    val = takeNext ? nv : (takeD ? ds : val);
                    idx = takeNext ? ni : (takeD ? js : idx);
                }
            } while (mA);
            thrA = __shfl_sync(0xffffffffu, val, 0);
        }
        if (mB) {
            do {
                int s = __ffs(mB) - 1;
                mB &= mB - 1;
                float ds = __shfl_sync(0xffffffffu, dB, s);
                int   js = (jj << 5) + s;
                float nv = __shfl_down_sync(0xffffffffu, val, 1, 16);
                int   ni = __shfl_down_sync(0xffffffffu, idx, 1, 16);
                if (sl == 15) { nv = -CUDART_INF_F; ni = -1; }
                bool takeNext = (nv >= ds);
                bool takeD    = (val >= ds);
                if (seg == 1) {
                    val = takeNext ? nv : (takeD ? ds : val);
                    idx = takeNext ? ni : (takeD ? js : idx);
                }
            } while (mB);
            thrB = __shfl_sync(0xffffffffu, val, 16);
        }
    }

    int q = q0 + seg;
    g_nbr[(size_t)q * KNNK + sl] = idx;
}

// ---------------- stage 2: influence + aggregation -> bf16 hi/lo ----------------
__global__ void agg_kernel(const float* __restrict__ kpts) {
    __shared__ int   nbr[KNNK];
    __shared__ float diffs[KNNK][3];
    __shared__ float kps[KP * 3];
    __shared__ float infl[KNNK][KP];

    int m   = blockIdx.x;
    int b   = m >> 12;
    int tid = threadIdx.x;

    if (tid < KP * 3) kps[tid] = kpts[tid];
    if (tid < KNNK)   nbr[tid] = g_nbr[(size_t)m * KNNK + tid];
    __syncthreads();
    if (tid < KNNK) {
        float4 qv = g_coordsT[m];
        float4 c  = g_coordsT[(b << 12) + nbr[tid]];
        diffs[tid][0] = c.x - qv.x;
        diffs[tid][1] = c.y - qv.y;
        diffs[tid][2] = c.z - qv.z;
    }
    __syncthreads();
    for (int t = tid; t < KNNK * KP; t += 64) {
        int kk = t / KP, p = t % KP;
        float dx = diffs[kk][0] - kps[p * 3 + 0];
        float dy = diffs[kk][1] - kps[p * 3 + 1];
        float dz = diffs[kk][2] - kps[p * 3 + 2];
        float sq = dx * dx + dy * dy + dz * dz;
        infl[kk][p] = expf(-sq * 100.0f);
    }
    __syncthreads();

    float a[KP];
    #pragma unroll
    for (int p = 0; p < KP; p++) a[p] = 0.0f;

    for (int kk = 0; kk < KNNK; kk++) {
        float f = g_featT[((size_t)(b << 12) + nbr[kk]) * CIN + tid];
        #pragma unroll
        for (int p = 0; p < KP; p++)
            a[p] += infl[kk][p] * f;
    }
    size_t rb = (size_t)m * KDIM + tid;
    #pragma unroll
    for (int p = 0; p < KP; p++) {
        float v = a[p];
        __nv_bfloat16 h = __float2bfloat16(v);
        __nv_bfloat16 l = __float2bfloat16(v - __bfloat162float(h));
        g_aggh[rb + p * CIN] = h;
        g_aggl[rb + p * CIN] = l;
    }
}

// ---------------- stage 3: mma.sync bf16 3-pass GEMM with fragment pipeline ----------------
#define KCH     64
#define NCHUNK  (KDIM / KCH)              // 15
#define ASTRIDE 72
#define TILE_B  (128 * ASTRIDE * 2)       // 18432
#define BUF_B   (4 * TILE_B)              // 73728
#define SMEM_DYN (2 * BUF_B)              // 147456

__device__ __forceinline__ void mma16816(float* c, const uint32_t* a, const uint32_t* b) {
    asm volatile(
        "mma.sync.aligned.m16n8k16.row.col.f32.bf16.bf16.f32 "
        "{%0,%1,%2,%3}, {%4,%5,%6,%7}, {%8,%9}, {%0,%1,%2,%3};"
        : "+f"(c[0]), "+f"(c[1]), "+f"(c[2]), "+f"(c[3])
        : "r"(a[0]), "r"(a[1]), "r"(a[2]), "r"(a[3]), "r"(b[0]), "r"(b[1]));
}

__global__ __launch_bounds__(256, 1) void gemm_kernel(const float* __restrict__ bias,
                                                      float* __restrict__ out) {
    extern __shared__ __align__(16) char smem[];
    int tid  = threadIdx.x;
    int warp = tid >> 5;
    int lane = tid & 31;
    int wm   = warp >> 2;
    int wn   = warp & 3;
    int g    = lane >> 2;
    int tig  = lane & 3;
    int m0   = blockIdx.x * 128;

    float acc[4][4][4];
    #pragma unroll
    for (int i = 0; i < 4; i++)
        #pragma unroll
        for (int j = 0; j < 4; j++)
            #pragma unroll
            for (int c = 0; c < 4; c++) acc[i][j][c] = 0.0f;

    const char* srcs[4] = {
        (const char*)g_aggh + (size_t)m0 * (KDIM * 2),
        (const char*)g_aggl + (size_t)m0 * (KDIM * 2),
        (const char*)g_wh,
        (const char*)g_wl };

    auto load_chunk = [&](int ch, int bufsel) {
        char* dst0 = smem + bufsel * BUF_B;
        size_t koff = (size_t)ch * (KCH * 2);
        #pragma unroll
        for (int i = 0; i < 16; i++) {
            int gi   = tid + 256 * i;
            int tile = gi >> 10;
            int wi   = gi & 1023;
            int r    = wi >> 3;
            int s    = wi & 7;
            uint4 v = *(const uint4*)(srcs[tile] + (size_t)r * (KDIM * 2) + koff + s * 16);
            *(uint4*)(dst0 + tile * TILE_B + r * (ASTRIDE * 2) + s * 16) = v;
        }
    };

    // fragment double-buffer
    uint32_t ah[2][4][4], al[2][4][4], bh[2][4][2], bl[2][4][2];

    auto load_frags = [&](int pb, int bufsel, int ks) {
        const uint32_t* Ah = (const uint32_t*)(smem + bufsel * BUF_B);
        const uint32_t* Al = (const uint32_t*)(smem + bufsel * BUF_B + TILE_B);
        const uint32_t* Bh = (const uint32_t*)(smem + bufsel * BUF_B + 2 * TILE_B);
        const uint32_t* Bl = (const uint32_t*)(smem + bufsel * BUF_B + 3 * TILE_B);
        int kb = ks * 8 + tig;
        #pragma unroll
        for (int mt = 0; mt < 4; mt++) {
            int r0 = (wm * 64 + mt * 16 + g) * (ASTRIDE / 2);
            int r1 = r0 + 8 * (ASTRIDE / 2);
            ah[pb][mt][0] = Ah[r0 + kb];     ah[pb][mt][1] = Ah[r1 + kb];
            ah[pb][mt][2] = Ah[r0 + kb + 4]; ah[pb][mt][3] = Ah[r1 + kb + 4];
            al[pb][mt][0] = Al[r0 + kb];     al[pb][mt][1] = Al[r1 + kb];
            al[pb][mt][2] = Al[r0 + kb + 4]; al[pb][mt][3] = Al[r1 + kb + 4];
        }
        #pragma unroll
        for (int nt = 0; nt < 4; nt++) {
            int r0 = (wn * 32 + nt * 8 + g) * (ASTRIDE / 2);
            bh[pb][nt][0] = Bh[r0 + kb]; bh[pb][nt][1] = Bh[r0 + kb + 4];
            bl[pb][nt][0] = Bl[r0 + kb]; bl[pb][nt][1] = Bl[r0 + kb + 4];
        }
    };

    load_chunk(0, 0);
    __syncthreads();

    for (int ch = 0; ch < NCHUNK; ch++) {
        int bufsel = ch & 1;
        load_frags(0, bufsel, 0);
        if (ch + 1 < NCHUNK) load_chunk(ch + 1, bufsel ^ 1);

        #pragma unroll
        for (int ks = 0; ks < KCH / 16; ks++) {
            int pf = ks & 1;
            if (ks < KCH / 16 - 1) load_frags(pf ^ 1, bufsel, ks + 1);
            #pragma unroll
            for (int mt = 0; mt < 4; mt++)
                #pragma unroll
                for (int nt = 0; nt < 4; nt++) {
                    mma16816(acc[mt][nt], ah[pf][mt], bh[pf][nt]);
                    mma16816(acc[mt][nt], ah[pf][mt], bl[pf][nt]);
                    mma16816(acc[mt][nt], al[pf][mt], bh[pf][nt]);
                }
        }
        __syncthreads();
    }

    // epilogue: stage [o][m] in smem (stride 132), coalesced float4 STG
    float* so = (float*)smem;
    #pragma unroll
    for (int mt = 0; mt < 4; mt++)
        #pragma unroll
        for (int nt = 0; nt < 4; nt++) {
            int m = wm * 64 + mt * 16 + g;
            int o = wn * 32 + nt * 8 + tig * 2;
            so[o * 132 + m]           = acc[mt][nt][0];
            so[(o + 1) * 132 + m]     = acc[mt][nt][1];
            so[o * 132 + m + 8]       = acc[mt][nt][2];
            so[(o + 1) * 132 + m + 8] = acc[mt][nt][3];
        }
    __syncthreads();

    int b    = m0 >> 12;
    int nptb = m0 & (NN - 1);
    #pragma unroll
    for (int i = 0; i < 16; i++) {
        int idx = tid + i * 256;
        int o   = idx >> 5;
        int m4  = (idx & 31) * 4;
        float bv = __ldg(&bias[o]);
        float4 v = *(float4*)&so[o * 132 + m4];
        v.x += bv; v.y += bv; v.z += bv; v.w += bv;
        *(float4*)(out + ((size_t)b * COUT + o) * NN + nptb + m4) = v;
    }
}

// ---------------- launch ----------------
extern "C" void kernel_launch(void* const* d_in, const int* in_sizes, int n_in,
                              void* d_out, int out_size) {
    const float* coords        = (const float*)d_in[0];
    const float* features      = (const float*)d_in[1];
    const float* kernel_points = (const float*)d_in[2];
    const float* kernel_w      = (const float*)d_in[3];
    const float* bias          = (const float*)d_in[4];
    float* out = (float*)d_out;

    static bool attr_set = false;
    if (!attr_set) {
        cudaFuncSetAttribute(gemm_kernel, cudaFuncAttributeMaxDynamicSharedMemorySize, SMEM_DYN);
        attr_set = true;
    }

    prep_kernel<<<64 + 1024 + 480, 256>>>(coords, features, kernel_w);
    knn_kernel<<<BB * NN / 16, 256>>>();
    agg_kernel<<<BB * NN, 64>>>(kernel_points);
    gemm_kernel<<<BB * NN / 128, 256, SMEM_DYN>>>(bias, out);
}